// round 4
// baseline (speedup 1.0000x reference)
#include <cuda_runtime.h>
#include <cuda_fp16.h>
#include <cstdint>
#include <cstddef>

#define BATCH 8192
#define DIN   4096
#define DOUT  4096

// fp16 scratch (module-load allocation; legal per harness rules)
__device__ __half g_Xh[(size_t)BATCH * DIN];   // 64 MB
__device__ __half g_Wh[(size_t)DOUT  * DIN];   // 32 MB

// ---------------------------------------------------------------------------
// Conversion kernels: fp32 -> fp16 (x), fp32*mask -> fp16 (w)
// ---------------------------------------------------------------------------
__global__ void convert_x_kernel(const float4* __restrict__ x, int n4) {
    int i = blockIdx.x * blockDim.x + threadIdx.x;
    if (i >= n4) return;
    float4 v = x[i];
    __half2 h0 = __floats2half2_rn(v.x, v.y);
    __half2 h1 = __floats2half2_rn(v.z, v.w);
    uint2 u;
    u.x = *reinterpret_cast<uint32_t*>(&h0);
    u.y = *reinterpret_cast<uint32_t*>(&h1);
    reinterpret_cast<uint2*>(g_Xh)[i] = u;
}

__global__ void convert_w_kernel(const float4* __restrict__ w,
                                 const float4* __restrict__ m, int n4) {
    int i = blockIdx.x * blockDim.x + threadIdx.x;
    if (i >= n4) return;
    float4 wv = w[i];
    float4 mv = m[i];
    __half2 h0 = __floats2half2_rn(wv.x * mv.x, wv.y * mv.y);
    __half2 h1 = __floats2half2_rn(wv.z * mv.z, wv.w * mv.w);
    uint2 u;
    u.x = *reinterpret_cast<uint32_t*>(&h0);
    u.y = *reinterpret_cast<uint32_t*>(&h1);
    reinterpret_cast<uint2*>(g_Wh)[i] = u;
}

// ---------------------------------------------------------------------------
// GEMM: out[8192,4096] = Xh @ Wh^T, fp16 in / fp32 accum via mma.sync.m16n8k16
// CTA tile 256x128x32, 8 warps (4M x 2N), warp tile 64x64, 6-stage cp.async,
// 1 CTA/SM (256 regs/thread -> acc[4][8][4] stays in registers, no spill).
// ---------------------------------------------------------------------------
static constexpr int TM = 256;
static constexpr int TN = 128;
static constexpr int STAGES  = 6;
static constexpr int STAGE_B = (TM + TN) * 64;     // 24 KB (A 16KB + B 8KB)
static constexpr int SMEM_B  = STAGES * STAGE_B;   // 144 KB

// 64B rows (32 halfs). 16B chunk c in 0..3, swizzle: chunk XOR (row>>1)&3 —
// conflict-free for both cp.async stores and ldmatrix reads.
__device__ __forceinline__ uint32_t sw_off(int row, int c16) {
    return (uint32_t)(row * 64 + (((c16 ^ ((row >> 1) & 3)) << 4)));
}

__device__ __forceinline__ uint32_t smem_u32(const void* p) {
    uint32_t a;
    asm("{ .reg .u64 t; cvta.to.shared.u64 t, %1; cvt.u32.u64 %0, t; }"
        : "=r"(a) : "l"(p));
    return a;
}

__device__ __forceinline__ void ldsm_x4(uint32_t* r, uint32_t addr) {
    asm volatile("ldmatrix.sync.aligned.m8n8.x4.shared.b16 {%0,%1,%2,%3}, [%4];"
                 : "=r"(r[0]), "=r"(r[1]), "=r"(r[2]), "=r"(r[3]) : "r"(addr));
}

__device__ __forceinline__ void mma16816(float* c, const uint32_t* a,
                                         uint32_t b0, uint32_t b1) {
    asm volatile(
        "mma.sync.aligned.m16n8k16.row.col.f32.f16.f16.f32 "
        "{%0,%1,%2,%3}, {%4,%5,%6,%7}, {%8,%9}, {%0,%1,%2,%3};"
        : "+f"(c[0]), "+f"(c[1]), "+f"(c[2]), "+f"(c[3])
        : "r"(a[0]), "r"(a[1]), "r"(a[2]), "r"(a[3]), "r"(b0), "r"(b1));
}

// Fill one stage: A = 256 rows x 64B, B = 128 rows x 64B. 1536 chunks / 256 thr
// = 6 cp.async per thread.
__device__ __forceinline__ void load_stage(uint32_t st_base, int slot,
                                           int k0, int m0, int n0, int tid) {
    uint32_t base = st_base + (uint32_t)slot * STAGE_B;
#pragma unroll
    for (int i = 0; i < 6; i++) {
        int cid = i * 256 + tid;            // 0..1535; A: <1024, B: >=1024
        const __half* gp;
        uint32_t so;
        if (cid < 1024) {                   // A: 256 rows x 4 chunks
            int row = cid >> 2, c = cid & 3;
            gp = g_Xh + (size_t)(m0 + row) * DIN + k0 + c * 8;
            so = base + sw_off(row, c);
        } else {                            // B: 128 rows x 4 chunks
            int row = (cid - 1024) >> 2, c = cid & 3;
            gp = g_Wh + (size_t)(n0 + row) * DIN + k0 + c * 8;
            so = base + (uint32_t)(TM * 64) + sw_off(row, c);
        }
        asm volatile("cp.async.cg.shared.global [%0], [%1], 16;"
                     :: "r"(so), "l"(gp) : "memory");
    }
    asm volatile("cp.async.commit_group;" ::: "memory");
}

__global__ void __launch_bounds__(256, 1)
expander_gemm_kernel(float* __restrict__ out) {
    extern __shared__ char smem_raw[];
    const uint32_t st_base = smem_u32(smem_raw);

    const int tid  = threadIdx.x;
    const int lane = tid & 31;
    const int warp = tid >> 5;
    const int wm = warp & 3;        // 4 warps along M
    const int wn = warp >> 2;       // 2 warps along N
    const int mbase = wm * 64;
    const int nbase = wn * 64;

    // Rasterization: 4 M-tiles x 32 N-tiles per group (~1 wave, 40MB in L2).
    const int TILES_N = DOUT / TN;                // 32
    const int per_g = 4 * TILES_N;                // 128
    int g   = blockIdx.x / per_g;
    int rem = blockIdx.x % per_g;
    int mt = g * 4 + (rem & 3);
    int nt = rem >> 2;
    const int m0 = mt * TM, n0 = nt * TN;

    // ldmatrix addressing. kk=1 address = kk0 ^ 32 (chunk+2 == XOR 2 in the
    // swizzle domain).
    const int a_row  = lane & 15;
    const int a_cadd = lane >> 4;
    const int b_row  = (lane & 7) + ((lane >> 3) & 1) * 8;
    const int b_cadd = lane >> 4;

    uint32_t offA[4], offB[4];
#pragma unroll
    for (int i4 = 0; i4 < 4; i4++) {
        int ra = mbase + i4 * 16 + a_row;
        offA[i4] = (uint32_t)ra * 64 + ((uint32_t)(a_cadd ^ ((ra >> 1) & 3)) << 4);
        int rb = nbase + i4 * 16 + b_row;
        offB[i4] = (uint32_t)(TM * 64) + (uint32_t)rb * 64
                 + ((uint32_t)(b_cadd ^ ((rb >> 1) & 3)) << 4);
    }

    float acc[4][8][4];
#pragma unroll
    for (int a = 0; a < 4; a++)
#pragma unroll
        for (int b = 0; b < 8; b++)
#pragma unroll
            for (int c = 0; c < 4; c++) acc[a][b][c] = 0.f;

    // Prologue: fill STAGES-1 stages.
#pragma unroll
    for (int s = 0; s < STAGES - 1; s++)
        load_stage(st_base, s, s * 32, m0, n0, tid);

    const int NSTEPS = DIN / 32;    // 128
#pragma unroll 1
    for (int ks = 0; ks < NSTEPS; ks++) {
        asm volatile("cp.async.wait_group 4;" ::: "memory");  // STAGES-2 pending
        __syncthreads();

        const uint32_t sb = st_base + (uint32_t)(ks % STAGES) * STAGE_B;

        // Refill next stage first: LDGSTS issue overlaps LDSM+HMMA below.
        int nxt = ks + STAGES - 1;
        if (nxt < NSTEPS)
            load_stage(st_base, nxt % STAGES, nxt * 32, m0, n0, tid);

#pragma unroll
        for (int kk = 0; kk < 2; kk++) {
            const uint32_t x32 = kk ? 32u : 0u;
            uint32_t A[4][4], B[4][4];
#pragma unroll
            for (int i4 = 0; i4 < 4; i4++) ldsm_x4(A[i4], (sb + offA[i4]) ^ x32);
#pragma unroll
            for (int i4 = 0; i4 < 4; i4++) ldsm_x4(B[i4], (sb + offB[i4]) ^ x32);
#pragma unroll
            for (int ai = 0; ai < 4; ai++)
#pragma unroll
                for (int bi = 0; bi < 4; bi++) {
                    mma16816(acc[ai][bi * 2 + 0], A[ai], B[bi][0], B[bi][2]);
                    mma16816(acc[ai][bi * 2 + 1], A[ai], B[bi][1], B[bi][3]);
                }
        }
    }

    // Epilogue: direct stores, 8B per lane per fragment pair.
    const int gid = lane >> 2, tig = lane & 3;
#pragma unroll
    for (int ai = 0; ai < 4; ai++) {
        int r0 = m0 + mbase + ai * 16 + gid;
#pragma unroll
        for (int j8 = 0; j8 < 8; j8++) {
            int col = n0 + nbase + j8 * 8 + tig * 2;
            float2 v0 = make_float2(acc[ai][j8][0], acc[ai][j8][1]);
            float2 v1 = make_float2(acc[ai][j8][2], acc[ai][j8][3]);
            *reinterpret_cast<float2*>(out + (size_t)r0 * DOUT + col) = v0;
            *reinterpret_cast<float2*>(out + (size_t)(r0 + 8) * DOUT + col) = v1;
        }
    }
}

// ---------------------------------------------------------------------------
// Launch
// ---------------------------------------------------------------------------
extern "C" void kernel_launch(void* const* d_in, const int* in_sizes, int n_in,
                              void* d_out, int out_size) {
    const float* x    = (const float*)d_in[0];
    const float* w    = (const float*)d_in[1];
    const float* mask = (const float*)d_in[2];
    float* out = (float*)d_out;

    {
        int n4 = (BATCH * DIN) / 4;
        convert_x_kernel<<<(n4 + 255) / 256, 256>>>((const float4*)x, n4);
    }
    {
        int n4 = (DOUT * DIN) / 4;
        convert_w_kernel<<<(n4 + 255) / 256, 256>>>((const float4*)w, (const float4*)mask, n4);
    }

    static bool attr_set = false;
    if (!attr_set) {
        cudaFuncSetAttribute(expander_gemm_kernel,
                             cudaFuncAttributeMaxDynamicSharedMemorySize, SMEM_B);
        attr_set = true;
    }
    int grid = (BATCH / TM) * (DOUT / TN);   // 1024
    expander_gemm_kernel<<<grid, 256, SMEM_B>>>(out);
}

// round 5
// speedup vs baseline: 1.1570x; 1.1570x over previous
#include <cuda_runtime.h>
#include <cuda_fp16.h>
#include <cstdint>
#include <cstddef>

#define BATCH 8192
#define DIN   4096
#define DOUT  4096

// fp16 scratch (module-load allocation; legal per harness rules)
__device__ __half g_Xh[(size_t)BATCH * DIN];   // 64 MB
__device__ __half g_Wh[(size_t)DOUT  * DIN];   // 32 MB

// ---------------------------------------------------------------------------
// Fused conversion kernel: x fp32->fp16 and w*mask fp32->fp16 in one launch.
// ---------------------------------------------------------------------------
static constexpr int NX4 = (BATCH * DIN) / 4;   // 8388608
static constexpr int NW4 = (DOUT  * DIN) / 4;   // 4194304

__global__ void convert_both_kernel(const float4* __restrict__ x,
                                    const float4* __restrict__ w,
                                    const float4* __restrict__ m) {
    int i = blockIdx.x * blockDim.x + threadIdx.x;
    if (i < NX4) {
        float4 v = x[i];
        __half2 h0 = __floats2half2_rn(v.x, v.y);
        __half2 h1 = __floats2half2_rn(v.z, v.w);
        uint2 u;
        u.x = *reinterpret_cast<uint32_t*>(&h0);
        u.y = *reinterpret_cast<uint32_t*>(&h1);
        reinterpret_cast<uint2*>(g_Xh)[i] = u;
    } else if (i < NX4 + NW4) {
        int j = i - NX4;
        float4 wv = w[j];
        float4 mv = m[j];
        __half2 h0 = __floats2half2_rn(wv.x * mv.x, wv.y * mv.y);
        __half2 h1 = __floats2half2_rn(wv.z * mv.z, wv.w * mv.w);
        uint2 u;
        u.x = *reinterpret_cast<uint32_t*>(&h0);
        u.y = *reinterpret_cast<uint32_t*>(&h1);
        reinterpret_cast<uint2*>(g_Wh)[j] = u;
    }
}

// ---------------------------------------------------------------------------
// GEMM: out[8192,4096] = Xh @ Wh^T, fp16 in / fp32 accum via mma.sync.m16n8k16
// CTA tile 128x128x32-per-stage, 8 warps (4M x 2N), warp tile 32x64.
// 6 stages, consume 2 stages (64 k) per outer iteration -> half the barriers.
// 2 CTAs/SM, regs <= 128 (same pressure as the R2 winner).
// ---------------------------------------------------------------------------
static constexpr int STAGES  = 6;
static constexpr int STAGE_B = 16384;              // A 8KB + B 8KB
static constexpr int SMEM_B  = STAGES * STAGE_B;   // 96 KB

// 64B rows (32 halfs). 16B chunk c in 0..3, swizzle chunk XOR (row>>1)&3.
__device__ __forceinline__ uint32_t sw_off(int row, int c16) {
    return (uint32_t)(row * 64 + (((c16 ^ ((row >> 1) & 3)) << 4)));
}

__device__ __forceinline__ uint32_t smem_u32(const void* p) {
    uint32_t a;
    asm("{ .reg .u64 t; cvta.to.shared.u64 t, %1; cvt.u32.u64 %0, t; }"
        : "=r"(a) : "l"(p));
    return a;
}

__device__ __forceinline__ void ldsm_x4(uint32_t& r0, uint32_t& r1,
                                        uint32_t& r2, uint32_t& r3, uint32_t addr) {
    asm volatile("ldmatrix.sync.aligned.m8n8.x4.shared.b16 {%0,%1,%2,%3}, [%4];"
                 : "=r"(r0), "=r"(r1), "=r"(r2), "=r"(r3) : "r"(addr));
}

__device__ __forceinline__ void mma16816(float* c, const uint32_t* a,
                                         uint32_t b0, uint32_t b1) {
    asm volatile(
        "mma.sync.aligned.m16n8k16.row.col.f32.f16.f16.f32 "
        "{%0,%1,%2,%3}, {%4,%5,%6,%7}, {%8,%9}, {%0,%1,%2,%3};"
        : "+f"(c[0]), "+f"(c[1]), "+f"(c[2]), "+f"(c[3])
        : "r"(a[0]), "r"(a[1]), "r"(a[2]), "r"(a[3]), "r"(b0), "r"(b1));
}

__device__ __forceinline__ void load_stage(uint32_t st_base, int slot,
                                           int k0, int m0, int n0, int tid) {
    uint32_t base = st_base + (uint32_t)slot * STAGE_B;
#pragma unroll
    for (int i = 0; i < 4; i++) {
        int cid = i * 256 + tid;            // 0..1023 (A: <512, B: >=512)
        const __half* gp;
        uint32_t so;
        if (cid < 512) {                    // A: 128 rows x 4 chunks
            int row = cid >> 2, c = cid & 3;
            gp = g_Xh + (size_t)(m0 + row) * DIN + k0 + c * 8;
            so = base + sw_off(row, c);
        } else {                            // B: 128 rows x 4 chunks
            int row = (cid - 512) >> 2, c = cid & 3;
            gp = g_Wh + (size_t)(n0 + row) * DIN + k0 + c * 8;
            so = base + 8192 + sw_off(row, c);
        }
        asm volatile("cp.async.cg.shared.global [%0], [%1], 16;"
                     :: "r"(so), "l"(gp) : "memory");
    }
    asm volatile("cp.async.commit_group;" ::: "memory");
}

__global__ void __launch_bounds__(256, 2)
expander_gemm_kernel(float* __restrict__ out) {
    extern __shared__ char smem_raw[];
    const uint32_t st_base = smem_u32(smem_raw);

    const int tid  = threadIdx.x;
    const int lane = tid & 31;
    const int warp = tid >> 5;
    const int wm = warp & 3;        // 4 warps along M
    const int wn = warp >> 2;       // 2 warps along N
    const int mbase = wm * 32;
    const int nbase = wn * 64;

    // Rasterization: groups of 8 M-tiles x all 32 N-tiles for L2 reuse.
    const int TILES_N = DOUT / 128;               // 32
    const int per_g = 8 * TILES_N;                // 256
    int g   = blockIdx.x / per_g;
    int rem = blockIdx.x % per_g;
    int mt = g * 8 + (rem & 7);
    int nt = rem >> 3;
    const int m0 = mt * 128, n0 = nt * 128;

    // Per-thread ldmatrix addressing (kk=1 addr = kk0 ^ 32 in swizzle domain).
    const int a_row  = lane & 15;
    const int a_cadd = lane >> 4;
    const int b_row  = (lane & 7) + ((lane >> 3) & 1) * 8;
    const int b_cadd = lane >> 4;

    int rA0 = mbase + a_row, rA1 = mbase + 16 + a_row;
    const uint32_t offA0 = (uint32_t)rA0 * 64 + ((uint32_t)(a_cadd ^ ((rA0 >> 1) & 3)) << 4);
    const uint32_t offA1 = (uint32_t)rA1 * 64 + ((uint32_t)(a_cadd ^ ((rA1 >> 1) & 3)) << 4);
    uint32_t offB[4];
#pragma unroll
    for (int i4 = 0; i4 < 4; i4++) {
        int r = nbase + i4 * 16 + b_row;
        offB[i4] = 8192u + (uint32_t)r * 64 + ((uint32_t)(b_cadd ^ ((r >> 1) & 3)) << 4);
    }

    float acc[2][8][4];
#pragma unroll
    for (int a = 0; a < 2; a++)
#pragma unroll
        for (int b = 0; b < 8; b++)
#pragma unroll
            for (int c = 0; c < 4; c++) acc[a][b][c] = 0.f;

    // Prologue: fill stages 0..3 (k-steps 0..3).
#pragma unroll
    for (int s = 0; s < 4; s++)
        load_stage(st_base, s, s * 32, m0, n0, tid);

    // 128 k-steps of 32, consumed 2 per outer iteration.
    int slot0 = 0;           // slot of first consumed stage this iter
#pragma unroll 1
    for (int t = 0; t < 64; t++) {
        asm volatile("cp.async.wait_group 2;" ::: "memory");  // 2 consumable ready
        __syncthreads();

        // Refill the two slots consumed last iteration with k-steps 2t+4, 2t+5.
        int kf = 2 * t + 4;
        if (kf < 128) {
            int fs = slot0 + 4; if (fs >= STAGES) fs -= STAGES;
            load_stage(st_base, fs, kf * 32, m0, n0, tid);
            fs = slot0 + 5; if (fs >= STAGES) fs -= STAGES;
            load_stage(st_base, fs, (kf + 1) * 32, m0, n0, tid);
        }

#pragma unroll
        for (int h = 0; h < 2; h++) {
            int s = slot0 + h; if (s >= STAGES) s -= STAGES;
            const uint32_t sb = st_base + (uint32_t)s * STAGE_B;
#pragma unroll
            for (int kk = 0; kk < 2; kk++) {
                const uint32_t x32 = kk ? 32u : 0u;
                uint32_t A0[4], A1[4];
                ldsm_x4(A0[0], A0[1], A0[2], A0[3], (sb + offA0) ^ x32);
                ldsm_x4(A1[0], A1[1], A1[2], A1[3], (sb + offA1) ^ x32);
                uint32_t Bf[4][4];
#pragma unroll
                for (int i4 = 0; i4 < 4; i4++)
                    ldsm_x4(Bf[i4][0], Bf[i4][1], Bf[i4][2], Bf[i4][3],
                            (sb + offB[i4]) ^ x32);
#pragma unroll
                for (int i4 = 0; i4 < 4; i4++) {
                    mma16816(acc[0][i4 * 2 + 0], A0, Bf[i4][0], Bf[i4][2]);
                    mma16816(acc[0][i4 * 2 + 1], A0, Bf[i4][1], Bf[i4][3]);
                    mma16816(acc[1][i4 * 2 + 0], A1, Bf[i4][0], Bf[i4][2]);
                    mma16816(acc[1][i4 * 2 + 1], A1, Bf[i4][1], Bf[i4][3]);
                }
            }
        }

        slot0 += 2; if (slot0 >= STAGES) slot0 -= STAGES;
    }

    // Epilogue: direct stores, 8B (2 floats) per lane per fragment pair.
    const int gid = lane >> 2, tig = lane & 3;
#pragma unroll
    for (int im = 0; im < 2; im++) {
        int r0 = m0 + mbase + im * 16 + gid;
#pragma unroll
        for (int j8 = 0; j8 < 8; j8++) {
            int col = n0 + nbase + j8 * 8 + tig * 2;
            float2 v0 = make_float2(acc[im][j8][0], acc[im][j8][1]);
            float2 v1 = make_float2(acc[im][j8][2], acc[im][j8][3]);
            *reinterpret_cast<float2*>(out + (size_t)r0 * DOUT + col) = v0;
            *reinterpret_cast<float2*>(out + (size_t)(r0 + 8) * DOUT + col) = v1;
        }
    }
}

// ---------------------------------------------------------------------------
// Launch
// ---------------------------------------------------------------------------
extern "C" void kernel_launch(void* const* d_in, const int* in_sizes, int n_in,
                              void* d_out, int out_size) {
    const float* x    = (const float*)d_in[0];
    const float* w    = (const float*)d_in[1];
    const float* mask = (const float*)d_in[2];
    float* out = (float*)d_out;

    {
        int ntot = NX4 + NW4;
        convert_both_kernel<<<(ntot + 255) / 256, 256>>>(
            (const float4*)x, (const float4*)w, (const float4*)mask);
    }

    static bool attr_set = false;
    if (!attr_set) {
        cudaFuncSetAttribute(expander_gemm_kernel,
                             cudaFuncAttributeMaxDynamicSharedMemorySize, SMEM_B);
        attr_set = true;
    }
    int grid = (BATCH / 128) * (DOUT / 128);   // 2048
    expander_gemm_kernel<<<grid, 256, SMEM_B>>>(out);
}

// round 6
// speedup vs baseline: 1.2259x; 1.0596x over previous
#include <cuda_runtime.h>
#include <cuda_fp16.h>
#include <cstdint>
#include <cstddef>

#define BATCH 8192
#define DIN   4096
#define DOUT  4096

// fp16 scratch (module-load allocation; legal per harness rules)
__device__ __half g_Xh[(size_t)BATCH * DIN];   // 64 MB
__device__ __half g_Wh[(size_t)DOUT  * DIN];   // 32 MB

// ---------------------------------------------------------------------------
// Fused conversion kernel: x fp32->fp16 and w*mask fp32->fp16 in one launch.
// ---------------------------------------------------------------------------
static constexpr int NX4 = (BATCH * DIN) / 4;   // 8388608
static constexpr int NW4 = (DOUT  * DIN) / 4;   // 4194304

__global__ void convert_both_kernel(const float4* __restrict__ x,
                                    const float4* __restrict__ w,
                                    const float4* __restrict__ m) {
    int i = blockIdx.x * blockDim.x + threadIdx.x;
    if (i < NX4) {
        float4 v = x[i];
        __half2 h0 = __floats2half2_rn(v.x, v.y);
        __half2 h1 = __floats2half2_rn(v.z, v.w);
        uint2 u;
        u.x = *reinterpret_cast<uint32_t*>(&h0);
        u.y = *reinterpret_cast<uint32_t*>(&h1);
        reinterpret_cast<uint2*>(g_Xh)[i] = u;
    } else if (i < NX4 + NW4) {
        int j = i - NX4;
        float4 wv = w[j];
        float4 mv = m[j];
        __half2 h0 = __floats2half2_rn(wv.x * mv.x, wv.y * mv.y);
        __half2 h1 = __floats2half2_rn(wv.z * mv.z, wv.w * mv.w);
        uint2 u;
        u.x = *reinterpret_cast<uint32_t*>(&h0);
        u.y = *reinterpret_cast<uint32_t*>(&h1);
        reinterpret_cast<uint2*>(g_Wh)[j] = u;
    }
}

// ---------------------------------------------------------------------------
// GEMM: out[8192,4096] = Xh @ Wh^T, fp16 in / fp32 accum via mma.sync.m16n8k16
// CTA tile 128x128x32-per-stage, 8 warps (4M x 2N), warp tile 32x64.
// 6 stages, consume 2 stages (64 k) per outer iteration.
// Inner body interleaves LDSM issue into the HMMA stream to overlap the
// smem crossbar (co-saturated at 128 B/cyc) with the tensor pipe.
// ---------------------------------------------------------------------------
static constexpr int STAGES  = 6;
static constexpr int STAGE_B = 16384;              // A 8KB + B 8KB
static constexpr int SMEM_B  = STAGES * STAGE_B;   // 96 KB

// 64B rows (32 halfs). 16B chunk c in 0..3, swizzle chunk XOR (row>>1)&3.
__device__ __forceinline__ uint32_t sw_off(int row, int c16) {
    return (uint32_t)(row * 64 + (((c16 ^ ((row >> 1) & 3)) << 4)));
}

__device__ __forceinline__ uint32_t smem_u32(const void* p) {
    uint32_t a;
    asm("{ .reg .u64 t; cvta.to.shared.u64 t, %1; cvt.u32.u64 %0, t; }"
        : "=r"(a) : "l"(p));
    return a;
}

__device__ __forceinline__ void ldsm_x4(uint32_t* r, uint32_t addr) {
    asm volatile("ldmatrix.sync.aligned.m8n8.x4.shared.b16 {%0,%1,%2,%3}, [%4];"
                 : "=r"(r[0]), "=r"(r[1]), "=r"(r[2]), "=r"(r[3]) : "r"(addr));
}

__device__ __forceinline__ void mma16816(float* c, const uint32_t* a,
                                         uint32_t b0, uint32_t b1) {
    asm volatile(
        "mma.sync.aligned.m16n8k16.row.col.f32.f16.f16.f32 "
        "{%0,%1,%2,%3}, {%4,%5,%6,%7}, {%8,%9}, {%0,%1,%2,%3};"
        : "+f"(c[0]), "+f"(c[1]), "+f"(c[2]), "+f"(c[3])
        : "r"(a[0]), "r"(a[1]), "r"(a[2]), "r"(a[3]), "r"(b0), "r"(b1));
}

__device__ __forceinline__ void load_stage(uint32_t st_base, int slot,
                                           int k0, int m0, int n0, int tid) {
    uint32_t base = st_base + (uint32_t)slot * STAGE_B;
#pragma unroll
    for (int i = 0; i < 4; i++) {
        int cid = i * 256 + tid;            // 0..1023 (A: <512, B: >=512)
        const __half* gp;
        uint32_t so;
        if (cid < 512) {                    // A: 128 rows x 4 chunks
            int row = cid >> 2, c = cid & 3;
            gp = g_Xh + (size_t)(m0 + row) * DIN + k0 + c * 8;
            so = base + sw_off(row, c);
        } else {                            // B: 128 rows x 4 chunks
            int row = (cid - 512) >> 2, c = cid & 3;
            gp = g_Wh + (size_t)(n0 + row) * DIN + k0 + c * 8;
            so = base + 8192 + sw_off(row, c);
        }
        asm volatile("cp.async.cg.shared.global [%0], [%1], 16;"
                     :: "r"(so), "l"(gp) : "memory");
    }
    asm volatile("cp.async.commit_group;" ::: "memory");
}

__global__ void __launch_bounds__(256, 2)
expander_gemm_kernel(float* __restrict__ out) {
    extern __shared__ char smem_raw[];
    const uint32_t st_base = smem_u32(smem_raw);

    const int tid  = threadIdx.x;
    const int lane = tid & 31;
    const int warp = tid >> 5;
    const int wm = warp & 3;        // 4 warps along M
    const int wn = warp >> 2;       // 2 warps along N
    const int mbase = wm * 32;
    const int nbase = wn * 64;

    // Rasterization: groups of 8 M-tiles x all 32 N-tiles for L2 reuse.
    const int TILES_N = DOUT / 128;               // 32
    const int per_g = 8 * TILES_N;                // 256
    int g   = blockIdx.x / per_g;
    int rem = blockIdx.x % per_g;
    int mt = g * 8 + (rem & 7);
    int nt = rem >> 3;
    const int m0 = mt * 128, n0 = nt * 128;

    // Per-thread ldmatrix addressing (kk=1 addr = kk0 ^ 32 in swizzle domain).
    const int a_row  = lane & 15;
    const int a_cadd = lane >> 4;
    const int b_row  = (lane & 7) + ((lane >> 3) & 1) * 8;
    const int b_cadd = lane >> 4;

    int rA0 = mbase + a_row, rA1 = mbase + 16 + a_row;
    const uint32_t offA0 = (uint32_t)rA0 * 64 + ((uint32_t)(a_cadd ^ ((rA0 >> 1) & 3)) << 4);
    const uint32_t offA1 = (uint32_t)rA1 * 64 + ((uint32_t)(a_cadd ^ ((rA1 >> 1) & 3)) << 4);
    uint32_t offB[4];
#pragma unroll
    for (int i4 = 0; i4 < 4; i4++) {
        int r = nbase + i4 * 16 + b_row;
        offB[i4] = 8192u + (uint32_t)r * 64 + ((uint32_t)(b_cadd ^ ((r >> 1) & 3)) << 4);
    }

    float acc[2][8][4];
#pragma unroll
    for (int a = 0; a < 2; a++)
#pragma unroll
        for (int b = 0; b < 8; b++)
#pragma unroll
            for (int c = 0; c < 4; c++) acc[a][b][c] = 0.f;

    // Prologue: fill stages 0..3 (k-steps 0..3).
#pragma unroll
    for (int s = 0; s < 4; s++)
        load_stage(st_base, s, s * 32, m0, n0, tid);

    // 128 k-steps of 32, consumed 2 per outer iteration.
    int slot0 = 0;
#pragma unroll 1
    for (int t = 0; t < 64; t++) {
        asm volatile("cp.async.wait_group 2;" ::: "memory");
        __syncthreads();

        int kf = 2 * t + 4;

#pragma unroll
        for (int h = 0; h < 2; h++) {
            int s = slot0 + h; if (s >= STAGES) s -= STAGES;
            const uint32_t sb = st_base + (uint32_t)s * STAGE_B;

            // Spread the refill LDGSTS issue: one stage-fill per h.
            if (kf + h < 128) {
                int fs = slot0 + 4 + h; if (fs >= STAGES) fs -= STAGES;
                load_stage(st_base, fs, (kf + h) * 32, m0, n0, tid);
            }

#pragma unroll
            for (int kk = 0; kk < 2; kk++) {
                const uint32_t x32 = kk ? 32u : 0u;
                uint32_t A0[4], A1[4], B0[4], B1[4], B2[4], B3[4];
                // Front-load only what the first HMMA quad needs...
                ldsm_x4(A0, (sb + offA0) ^ x32);
                ldsm_x4(A1, (sb + offA1) ^ x32);
                ldsm_x4(B0, (sb + offB[0]) ^ x32);
                ldsm_x4(B1, (sb + offB[1]) ^ x32);
                // ...then interleave remaining LDSMs into the HMMA stream.
                mma16816(acc[0][0], A0, B0[0], B0[2]);
                mma16816(acc[0][1], A0, B0[1], B0[3]);
                ldsm_x4(B2, (sb + offB[2]) ^ x32);
                mma16816(acc[1][0], A1, B0[0], B0[2]);
                mma16816(acc[1][1], A1, B0[1], B0[3]);
                mma16816(acc[0][2], A0, B1[0], B1[2]);
                mma16816(acc[0][3], A0, B1[1], B1[3]);
                ldsm_x4(B3, (sb + offB[3]) ^ x32);
                mma16816(acc[1][2], A1, B1[0], B1[2]);
                mma16816(acc[1][3], A1, B1[1], B1[3]);
                mma16816(acc[0][4], A0, B2[0], B2[2]);
                mma16816(acc[0][5], A0, B2[1], B2[3]);
                mma16816(acc[1][4], A1, B2[0], B2[2]);
                mma16816(acc[1][5], A1, B2[1], B2[3]);
                mma16816(acc[0][6], A0, B3[0], B3[2]);
                mma16816(acc[0][7], A0, B3[1], B3[3]);
                mma16816(acc[1][6], A1, B3[0], B3[2]);
                mma16816(acc[1][7], A1, B3[1], B3[3]);
            }
        }

        slot0 += 2; if (slot0 >= STAGES) slot0 -= STAGES;
    }

    // Epilogue: direct stores, 8B (2 floats) per lane per fragment pair.
    const int gid = lane >> 2, tig = lane & 3;
#pragma unroll
    for (int im = 0; im < 2; im++) {
        int r0 = m0 + mbase + im * 16 + gid;
#pragma unroll
        for (int j8 = 0; j8 < 8; j8++) {
            int col = n0 + nbase + j8 * 8 + tig * 2;
            float2 v0 = make_float2(acc[im][j8][0], acc[im][j8][1]);
            float2 v1 = make_float2(acc[im][j8][2], acc[im][j8][3]);
            *reinterpret_cast<float2*>(out + (size_t)r0 * DOUT + col) = v0;
            *reinterpret_cast<float2*>(out + (size_t)(r0 + 8) * DOUT + col) = v1;
        }
    }
}

// ---------------------------------------------------------------------------
// Launch
// ---------------------------------------------------------------------------
extern "C" void kernel_launch(void* const* d_in, const int* in_sizes, int n_in,
                              void* d_out, int out_size) {
    const float* x    = (const float*)d_in[0];
    const float* w    = (const float*)d_in[1];
    const float* mask = (const float*)d_in[2];
    float* out = (float*)d_out;

    {
        int ntot = NX4 + NW4;
        convert_both_kernel<<<(ntot + 255) / 256, 256>>>(
            (const float4*)x, (const float4*)w, (const float4*)mask);
    }

    static bool attr_set = false;
    if (!attr_set) {
        cudaFuncSetAttribute(expander_gemm_kernel,
                             cudaFuncAttributeMaxDynamicSharedMemorySize, SMEM_B);
        attr_set = true;
    }
    int grid = (BATCH / 128) * (DOUT / 128);   // 2048
    expander_gemm_kernel<<<grid, 256, SMEM_B>>>(out);
}

// round 7
// speedup vs baseline: 1.2507x; 1.0202x over previous
#include <cuda_runtime.h>
#include <cuda_fp16.h>
#include <cstdint>
#include <cstddef>

#define BATCH 8192
#define DIN   4096
#define DOUT  4096

// fp16 scratch (module-load allocation; legal per harness rules)
__device__ __half g_Xh[(size_t)BATCH * DIN];   // 64 MB
__device__ __half g_Wh[(size_t)DOUT  * DIN];   // 32 MB

// ---------------------------------------------------------------------------
// Fused conversion kernel: x fp32->fp16 and w*mask fp32->fp16 in one launch.
// ---------------------------------------------------------------------------
static constexpr int NX4 = (BATCH * DIN) / 4;   // 8388608
static constexpr int NW4 = (DOUT  * DIN) / 4;   // 4194304

__global__ void convert_both_kernel(const float4* __restrict__ x,
                                    const float4* __restrict__ w,
                                    const float4* __restrict__ m) {
    int i = blockIdx.x * blockDim.x + threadIdx.x;
    if (i < NX4) {
        float4 v = x[i];
        __half2 h0 = __floats2half2_rn(v.x, v.y);
        __half2 h1 = __floats2half2_rn(v.z, v.w);
        uint2 u;
        u.x = *reinterpret_cast<uint32_t*>(&h0);
        u.y = *reinterpret_cast<uint32_t*>(&h1);
        reinterpret_cast<uint2*>(g_Xh)[i] = u;
    } else if (i < NX4 + NW4) {
        int j = i - NX4;
        float4 wv = w[j];
        float4 mv = m[j];
        __half2 h0 = __floats2half2_rn(wv.x * mv.x, wv.y * mv.y);
        __half2 h1 = __floats2half2_rn(wv.z * mv.z, wv.w * mv.w);
        uint2 u;
        u.x = *reinterpret_cast<uint32_t*>(&h0);
        u.y = *reinterpret_cast<uint32_t*>(&h1);
        reinterpret_cast<uint2*>(g_Wh)[j] = u;
    }
}

// ---------------------------------------------------------------------------
// GEMM: out[8192,4096] = Xh @ Wh^T, fp16 in / fp32 accum via mma.sync.m16n8k16
// CTA tile 128x128x32-per-stage, 8 warps (4M x 2N), warp tile 32x64.
// 6 stages, consume 2 stages (4 k16 chunks) per outer iteration.
// Rolling fragment prefetch: each chunk's HMMA stream issues the NEXT chunk's
// A0/A1/B0/B1 LDSMs, so only 1 of 4 chunk entries exposes LDSM latency.
// ---------------------------------------------------------------------------
static constexpr int STAGES  = 6;
static constexpr int STAGE_B = 16384;              // A 8KB + B 8KB
static constexpr int SMEM_B  = STAGES * STAGE_B;   // 96 KB

// 64B rows (32 halfs). 16B chunk c in 0..3, swizzle chunk XOR (row>>1)&3.
__device__ __forceinline__ uint32_t sw_off(int row, int c16) {
    return (uint32_t)(row * 64 + (((c16 ^ ((row >> 1) & 3)) << 4)));
}

__device__ __forceinline__ uint32_t smem_u32(const void* p) {
    uint32_t a;
    asm("{ .reg .u64 t; cvta.to.shared.u64 t, %1; cvt.u32.u64 %0, t; }"
        : "=r"(a) : "l"(p));
    return a;
}

__device__ __forceinline__ void ldsm_x4(uint32_t* r, uint32_t addr) {
    asm volatile("ldmatrix.sync.aligned.m8n8.x4.shared.b16 {%0,%1,%2,%3}, [%4];"
                 : "=r"(r[0]), "=r"(r[1]), "=r"(r[2]), "=r"(r[3]) : "r"(addr));
}

__device__ __forceinline__ void mma16816(float* c, const uint32_t* a,
                                         uint32_t b0, uint32_t b1) {
    asm volatile(
        "mma.sync.aligned.m16n8k16.row.col.f32.f16.f16.f32 "
        "{%0,%1,%2,%3}, {%4,%5,%6,%7}, {%8,%9}, {%0,%1,%2,%3};"
        : "+f"(c[0]), "+f"(c[1]), "+f"(c[2]), "+f"(c[3])
        : "r"(a[0]), "r"(a[1]), "r"(a[2]), "r"(a[3]), "r"(b0), "r"(b1));
}

__device__ __forceinline__ void load_stage(uint32_t st_base, int slot,
                                           int k0, int m0, int n0, int tid) {
    uint32_t base = st_base + (uint32_t)slot * STAGE_B;
#pragma unroll
    for (int i = 0; i < 4; i++) {
        int cid = i * 256 + tid;            // 0..1023 (A: <512, B: >=512)
        const __half* gp;
        uint32_t so;
        if (cid < 512) {                    // A: 128 rows x 4 chunks
            int row = cid >> 2, c = cid & 3;
            gp = g_Xh + (size_t)(m0 + row) * DIN + k0 + c * 8;
            so = base + sw_off(row, c);
        } else {                            // B: 128 rows x 4 chunks
            int row = (cid - 512) >> 2, c = cid & 3;
            gp = g_Wh + (size_t)(n0 + row) * DIN + k0 + c * 8;
            so = base + 8192 + sw_off(row, c);
        }
        asm volatile("cp.async.cg.shared.global [%0], [%1], 16;"
                     :: "r"(so), "l"(gp) : "memory");
    }
    asm volatile("cp.async.commit_group;" ::: "memory");
}

// Fragment set for one k16 chunk: A halves + first two B quads.
struct FragPre {
    uint32_t A0[4], A1[4], B0[4], B1[4];
};

__device__ __forceinline__ void ld_pre(FragPre& f, uint32_t sb, uint32_t x,
                                       uint32_t offA0, uint32_t offA1,
                                       const uint32_t* offB) {
    ldsm_x4(f.A0, (sb + offA0) ^ x);
    ldsm_x4(f.A1, (sb + offA1) ^ x);
    ldsm_x4(f.B0, (sb + offB[0]) ^ x);
    ldsm_x4(f.B1, (sb + offB[1]) ^ x);
}

// Process one k16 chunk (16 HMMAs). Loads its own B2/B3 and, if HAS_NEXT,
// the next chunk's pre-fragments, all interleaved into the HMMA stream.
template <bool HAS_NEXT>
__device__ __forceinline__ void chunk(float acc[2][8][4], FragPre& cur, FragPre& nxt,
                                      uint32_t sb, uint32_t x,
                                      uint32_t nsb, uint32_t nx,
                                      uint32_t offA0, uint32_t offA1,
                                      const uint32_t* offB) {
    uint32_t B2[4], B3[4];
    ldsm_x4(B2, (sb + offB[2]) ^ x);
    mma16816(acc[0][0], cur.A0, cur.B0[0], cur.B0[2]);
    mma16816(acc[0][1], cur.A0, cur.B0[1], cur.B0[3]);
    ldsm_x4(B3, (sb + offB[3]) ^ x);
    mma16816(acc[1][0], cur.A1, cur.B0[0], cur.B0[2]);
    mma16816(acc[1][1], cur.A1, cur.B0[1], cur.B0[3]);
    if (HAS_NEXT) ldsm_x4(nxt.A0, (nsb + offA0) ^ nx);
    mma16816(acc[0][2], cur.A0, cur.B1[0], cur.B1[2]);
    mma16816(acc[0][3], cur.A0, cur.B1[1], cur.B1[3]);
    if (HAS_NEXT) ldsm_x4(nxt.A1, (nsb + offA1) ^ nx);
    mma16816(acc[1][2], cur.A1, cur.B1[0], cur.B1[2]);
    mma16816(acc[1][3], cur.A1, cur.B1[1], cur.B1[3]);
    if (HAS_NEXT) ldsm_x4(nxt.B0, (nsb + offB[0]) ^ nx);
    mma16816(acc[0][4], cur.A0, B2[0], B2[2]);
    mma16816(acc[0][5], cur.A0, B2[1], B2[3]);
    if (HAS_NEXT) ldsm_x4(nxt.B1, (nsb + offB[1]) ^ nx);
    mma16816(acc[1][4], cur.A1, B2[0], B2[2]);
    mma16816(acc[1][5], cur.A1, B2[1], B2[3]);
    mma16816(acc[0][6], cur.A0, B3[0], B3[2]);
    mma16816(acc[0][7], cur.A0, B3[1], B3[3]);
    mma16816(acc[1][6], cur.A1, B3[0], B3[2]);
    mma16816(acc[1][7], cur.A1, B3[1], B3[3]);
}

__global__ void __launch_bounds__(256, 2)
expander_gemm_kernel(float* __restrict__ out) {
    extern __shared__ char smem_raw[];
    const uint32_t st_base = smem_u32(smem_raw);

    const int tid  = threadIdx.x;
    const int lane = tid & 31;
    const int warp = tid >> 5;
    const int wm = warp & 3;        // 4 warps along M
    const int wn = warp >> 2;       // 2 warps along N
    const int mbase = wm * 32;
    const int nbase = wn * 64;

    // Rasterization: groups of 8 M-tiles x all 32 N-tiles for L2 reuse.
    const int TILES_N = DOUT / 128;               // 32
    const int per_g = 8 * TILES_N;                // 256
    int g   = blockIdx.x / per_g;
    int rem = blockIdx.x % per_g;
    int mt = g * 8 + (rem & 7);
    int nt = rem >> 3;
    const int m0 = mt * 128, n0 = nt * 128;

    // Per-thread ldmatrix addressing (kk=1 addr = kk0 ^ 32 in swizzle domain).
    const int a_row  = lane & 15;
    const int a_cadd = lane >> 4;
    const int b_row  = (lane & 7) + ((lane >> 3) & 1) * 8;
    const int b_cadd = lane >> 4;

    int rA0 = mbase + a_row, rA1 = mbase + 16 + a_row;
    const uint32_t offA0 = (uint32_t)rA0 * 64 + ((uint32_t)(a_cadd ^ ((rA0 >> 1) & 3)) << 4);
    const uint32_t offA1 = (uint32_t)rA1 * 64 + ((uint32_t)(a_cadd ^ ((rA1 >> 1) & 3)) << 4);
    uint32_t offB[4];
#pragma unroll
    for (int i4 = 0; i4 < 4; i4++) {
        int r = nbase + i4 * 16 + b_row;
        offB[i4] = 8192u + (uint32_t)r * 64 + ((uint32_t)(b_cadd ^ ((r >> 1) & 3)) << 4);
    }

    float acc[2][8][4];
#pragma unroll
    for (int a = 0; a < 2; a++)
#pragma unroll
        for (int b = 0; b < 8; b++)
#pragma unroll
            for (int c = 0; c < 4; c++) acc[a][b][c] = 0.f;

    // Prologue: fill stages 0..3 (k-steps 0..3).
#pragma unroll
    for (int s = 0; s < 4; s++)
        load_stage(st_base, s, s * 32, m0, n0, tid);

    // 128 k-steps of 32, consumed 2 (= 4 k16 chunks) per outer iteration.
    int slot0 = 0;
#pragma unroll 1
    for (int t = 0; t < 64; t++) {
        asm volatile("cp.async.wait_group 2;" ::: "memory");
        __syncthreads();

        int s1 = slot0 + 1; if (s1 >= STAGES) s1 -= STAGES;
        const uint32_t sb0 = st_base + (uint32_t)slot0 * STAGE_B;
        const uint32_t sb1 = st_base + (uint32_t)s1 * STAGE_B;
        int kf = 2 * t + 4;

        FragPre f0, f1;
        // Chunk 0 entry: only latency-exposed LDSMs of the iteration.
        ld_pre(f0, sb0, 0u, offA0, offA1, offB);

        // Refill slot consumed 2 iters ago (split across the iteration as R6).
        if (kf < 128) {
            int fs = slot0 + 4; if (fs >= STAGES) fs -= STAGES;
            load_stage(st_base, fs, kf * 32, m0, n0, tid);
        }

        chunk<true >(acc, f0, f1, sb0, 0u,  sb0, 32u, offA0, offA1, offB);
        chunk<true >(acc, f1, f0, sb0, 32u, sb1, 0u,  offA0, offA1, offB);

        if (kf + 1 < 128) {
            int fs = slot0 + 5; if (fs >= STAGES) fs -= STAGES;
            load_stage(st_base, fs, (kf + 1) * 32, m0, n0, tid);
        }

        chunk<true >(acc, f0, f1, sb1, 0u,  sb1, 32u, offA0, offA1, offB);
        chunk<false>(acc, f1, f0, sb1, 32u, sb1, 32u, offA0, offA1, offB);

        slot0 += 2; if (slot0 >= STAGES) slot0 -= STAGES;
    }

    // Epilogue: direct stores, 8B (2 floats) per lane per fragment pair.
    const int gid = lane >> 2, tig = lane & 3;
#pragma unroll
    for (int im = 0; im < 2; im++) {
        int r0 = m0 + mbase + im * 16 + gid;
#pragma unroll
        for (int j8 = 0; j8 < 8; j8++) {
            int col = n0 + nbase + j8 * 8 + tig * 2;
            float2 v0 = make_float2(acc[im][j8][0], acc[im][j8][1]);
            float2 v1 = make_float2(acc[im][j8][2], acc[im][j8][3]);
            *reinterpret_cast<float2*>(out + (size_t)r0 * DOUT + col) = v0;
            *reinterpret_cast<float2*>(out + (size_t)(r0 + 8) * DOUT + col) = v1;
        }
    }
}

// ---------------------------------------------------------------------------
// Launch
// ---------------------------------------------------------------------------
extern "C" void kernel_launch(void* const* d_in, const int* in_sizes, int n_in,
                              void* d_out, int out_size) {
    const float* x    = (const float*)d_in[0];
    const float* w    = (const float*)d_in[1];
    const float* mask = (const float*)d_in[2];
    float* out = (float*)d_out;

    {
        int ntot = NX4 + NW4;
        convert_both_kernel<<<(ntot + 255) / 256, 256>>>(
            (const float4*)x, (const float4*)w, (const float4*)mask);
    }

    static bool attr_set = false;
    if (!attr_set) {
        cudaFuncSetAttribute(expander_gemm_kernel,
                             cudaFuncAttributeMaxDynamicSharedMemorySize, SMEM_B);
        attr_set = true;
    }
    int grid = (BATCH / 128) * (DOUT / 128);   // 2048
    expander_gemm_kernel<<<grid, 256, SMEM_B>>>(out);
}